// round 2
// baseline (speedup 1.0000x reference)
#include <cuda_runtime.h>

#define B_TOT   8192
#define T_STEPS 100
#define IN_DIM  32
#define H_DIM   32
#define HID     20
#define NRK     8

// tanh(x) = 1 - 2/(exp(2x)+1); exact at +-inf, ~1e-7 abs err elsewhere.
__device__ __forceinline__ float ftanh(float x) {
    float e = __expf(2.0f * x);
    return 1.0f - __fdividef(2.0f, e + 1.0f);
}

// One ODE-func eval: u = tanh( relu( zc@W1z + c ) @ W2 + b2 ), distributed over
// 4 threads per element. Each thread owns 8 input lanes (zc) and 8 output lanes.
__device__ __forceinline__ void feval(const float zc[8], const float c[HID],
                                      const float* sW1z, const float* sW2,
                                      const float* sbf2, int base, float u[8])
{
    float r[HID];
#pragma unroll
    for (int j = 0; j < HID; ++j) {
        const float4* w = reinterpret_cast<const float4*>(sW1z + j * 32 + base);
        float4 wa = w[0], wb = w[1];
        r[j] = zc[0]*wa.x + zc[1]*wa.y + zc[2]*wa.z + zc[3]*wa.w
             + zc[4]*wb.x + zc[5]*wb.y + zc[6]*wb.z + zc[7]*wb.w;
    }
#pragma unroll
    for (int j = 0; j < HID; ++j) {
        float v = r[j];
        v += __shfl_xor_sync(0xffffffffu, v, 1);
        v += __shfl_xor_sync(0xffffffffu, v, 2);
        r[j] = fmaxf(v + c[j], 0.0f);
    }
    float a[8];
#pragma unroll
    for (int o = 0; o < 8; ++o) a[o] = sbf2[base + o];
#pragma unroll
    for (int j = 0; j < HID; ++j) {
        const float4* w = reinterpret_cast<const float4*>(sW2 + j * 32 + base);
        float4 wa = w[0], wb = w[1];
        a[0] += r[j]*wa.x; a[1] += r[j]*wa.y; a[2] += r[j]*wa.z; a[3] += r[j]*wa.w;
        a[4] += r[j]*wb.x; a[5] += r[j]*wb.y; a[6] += r[j]*wb.z; a[7] += r[j]*wb.w;
    }
#pragma unroll
    for (int o = 0; o < 8; ++o) u[o] = ftanh(a[o]);
}

__global__ __launch_bounds__(128)
void latode_kernel(const float* __restrict__ dt,  const float* __restrict__ x,
                   const float* __restrict__ We1, const float* __restrict__ be1,
                   const float* __restrict__ We2, const float* __restrict__ be2,
                   const float* __restrict__ Wf1, const float* __restrict__ bf1,
                   const float* __restrict__ Wf2, const float* __restrict__ bf2,
                   const float* __restrict__ Wm1, const float* __restrict__ bm1,
                   const float* __restrict__ Wm2, const float* __restrict__ bm2,
                   float* __restrict__ out)
{
    // Transposed / natural weight copies in shared, 16B-aligned for LDS.128.
    __shared__ __align__(16) float sW1z[HID * 32];   // [j][i]  (z-part of Wf1, transposed)
    __shared__ __align__(16) float sW1x[HID * 32];   // [j][i]  (x-part of Wf1, transposed)
    __shared__ __align__(16) float sW2 [HID * 32];   // [j][o]  (Wf2 natural)
    __shared__ __align__(16) float sWe1T[10 * 32];   // [m][i]
    __shared__ __align__(16) float sWe2 [10 * 32];   // [m][o]
    __shared__ __align__(16) float sWm1T[10 * 32];   // [m][i]
    __shared__ float sbf1[HID], sbf2[32], sbe1[10], sbe2[32], sbm1[10], sWm2v[10], sbm2;

    const int tid = threadIdx.x;
    for (int idx = tid; idx < HID * 32; idx += blockDim.x) {
        int j = idx >> 5, i = idx & 31;
        sW1z[idx] = Wf1[i * HID + j];
        sW1x[idx] = Wf1[(32 + i) * HID + j];
        sW2[idx]  = Wf2[j * 32 + i];
    }
    for (int idx = tid; idx < 10 * 32; idx += blockDim.x) {
        int m = idx >> 5, i = idx & 31;
        sWe1T[idx] = We1[i * 10 + m];
        sWe2[idx]  = We2[m * 32 + i];
        sWm1T[idx] = Wm1[i * 10 + m];
    }
    if (tid < HID) sbf1[tid] = bf1[tid];
    if (tid < 32)  { sbf2[tid] = bf2[tid]; sbe2[tid] = be2[tid]; }
    if (tid < 10)  { sbe1[tid] = be1[tid]; sbm1[tid] = bm1[tid]; sWm2v[tid] = Wm2[tid]; }
    if (tid == 0)  sbm2 = bm2[0];
    __syncthreads();

    const int gt   = blockIdx.x * blockDim.x + tid;
    const int b    = gt >> 2;        // element id
    const int base = (gt & 3) * 8;   // owned lane window [base, base+8)
    const int g    = gt & 3;

    const float hs = 1.0f / NRK;

    // ---- encoder: z0 = tanh(tanh(x0@We1+be1)@We2+be2) ----
    float xr[8];
    {
        const float4* xp = reinterpret_cast<const float4*>(x + (size_t)b * T_STEPS * IN_DIM + base);
        float4 xa = xp[0], xb = xp[1];
        xr[0]=xa.x; xr[1]=xa.y; xr[2]=xa.z; xr[3]=xa.w;
        xr[4]=xb.x; xr[5]=xb.y; xr[6]=xb.z; xr[7]=xb.w;
    }
    float h10[10];
#pragma unroll
    for (int m = 0; m < 10; ++m) {
        const float4* w = reinterpret_cast<const float4*>(sWe1T + m * 32 + base);
        float4 wa = w[0], wb = w[1];
        float s = xr[0]*wa.x + xr[1]*wa.y + xr[2]*wa.z + xr[3]*wa.w
                + xr[4]*wb.x + xr[5]*wb.y + xr[6]*wb.z + xr[7]*wb.w;
        s += __shfl_xor_sync(0xffffffffu, s, 1);
        s += __shfl_xor_sync(0xffffffffu, s, 2);
        h10[m] = ftanh(s + sbe1[m]);
    }
    float z[8];
#pragma unroll
    for (int o = 0; o < 8; ++o) {
        float s = sbe2[base + o];
#pragma unroll
        for (int m = 0; m < 10; ++m) s += h10[m] * sWe2[m * 32 + base + o];
        z[o] = ftanh(s);
    }

    // ---- time loop ----
    for (int t = 0; t < T_STEPS; ++t) {
        {   // x_i for this step
            const float4* xp = reinterpret_cast<const float4*>(
                x + ((size_t)b * T_STEPS + t) * IN_DIM + base);
            float4 xa = xp[0], xb = xp[1];
            xr[0]=xa.x; xr[1]=xa.y; xr[2]=xa.z; xr[3]=xa.w;
            xr[4]=xb.x; xr[5]=xb.y; xr[6]=xb.z; xr[7]=xb.w;
        }
        const float2 dpair = *reinterpret_cast<const float2*>(dt + ((size_t)b * T_STEPS + t) * 2);
        const float sc = (dpair.y - dpair.x) * 0.01f;   // d * DT_SCALER
        const float ah = 0.5f * hs * sc;                 // half-step scale
        const float af = hs * sc;                        // full-step scale
        const float a6 = (hs / 6.0f) * sc;               // combine scale

        // c[j] = (x_i @ W1x)[j] + bf1[j]  — constant over all 32 f-evals this step
        float c[HID];
#pragma unroll
        for (int j = 0; j < HID; ++j) {
            const float4* w = reinterpret_cast<const float4*>(sW1x + j * 32 + base);
            float4 wa = w[0], wb = w[1];
            float s = xr[0]*wa.x + xr[1]*wa.y + xr[2]*wa.z + xr[3]*wa.w
                    + xr[4]*wb.x + xr[5]*wb.y + xr[6]*wb.z + xr[7]*wb.w;
            s += __shfl_xor_sync(0xffffffffu, s, 1);
            s += __shfl_xor_sync(0xffffffffu, s, 2);
            c[j] = s + sbf1[j];
        }

        for (int rk = 0; rk < NRK; ++rk) {
            float u[8], su[8], zc[8];
            feval(z, c, sW1z, sW2, sbf2, base, u);            // k1
#pragma unroll
            for (int l = 0; l < 8; ++l) { su[l] = u[l]; zc[l] = z[l] + ah * u[l]; }
            feval(zc, c, sW1z, sW2, sbf2, base, u);           // k2
#pragma unroll
            for (int l = 0; l < 8; ++l) { su[l] += 2.0f * u[l]; zc[l] = z[l] + ah * u[l]; }
            feval(zc, c, sW1z, sW2, sbf2, base, u);           // k3
#pragma unroll
            for (int l = 0; l < 8; ++l) { su[l] += 2.0f * u[l]; zc[l] = z[l] + af * u[l]; }
            feval(zc, c, sW1z, sW2, sbf2, base, u);           // k4
#pragma unroll
            for (int l = 0; l < 8; ++l) z[l] += a6 * (su[l] + u[l]);
        }

        // mu = tanh(z@Wm1+bm1)@Wm2 + bm2
        float hm[10];
#pragma unroll
        for (int m = 0; m < 10; ++m) {
            const float4* w = reinterpret_cast<const float4*>(sWm1T + m * 32 + base);
            float4 wa = w[0], wb = w[1];
            float s = z[0]*wa.x + z[1]*wa.y + z[2]*wa.z + z[3]*wa.w
                    + z[4]*wb.x + z[5]*wb.y + z[6]*wb.z + z[7]*wb.w;
            s += __shfl_xor_sync(0xffffffffu, s, 1);
            s += __shfl_xor_sync(0xffffffffu, s, 2);
            hm[m] = ftanh(s + sbm1[m]);
        }
        float mu = sbm2;
#pragma unroll
        for (int m = 0; m < 10; ++m) mu += hm[m] * sWm2v[m];
        if (g == 0) out[(size_t)b * T_STEPS + t] = mu;
    }
}

extern "C" void kernel_launch(void* const* d_in, const int* in_sizes, int n_in,
                              void* d_out, int out_size)
{
    const float* dt  = (const float*)d_in[0];
    const float* x   = (const float*)d_in[1];
    const float* We1 = (const float*)d_in[2];
    const float* be1 = (const float*)d_in[3];
    const float* We2 = (const float*)d_in[4];
    const float* be2 = (const float*)d_in[5];
    const float* Wf1 = (const float*)d_in[6];
    const float* bf1 = (const float*)d_in[7];
    const float* Wf2 = (const float*)d_in[8];
    const float* bf2 = (const float*)d_in[9];
    const float* Wm1 = (const float*)d_in[10];
    const float* bm1 = (const float*)d_in[11];
    const float* Wm2 = (const float*)d_in[12];
    const float* bm2 = (const float*)d_in[13];
    float* out = (float*)d_out;

    // 4 threads per batch element: 8192*4 = 32768 threads
    dim3 block(128);
    dim3 grid((B_TOT * 4) / 128);
    latode_kernel<<<grid, block>>>(dt, x, We1, be1, We2, be2,
                                   Wf1, bf1, Wf2, bf2, Wm1, bm1, Wm2, bm2, out);
}